// round 16
// baseline (speedup 1.0000x reference)
#include <cuda_runtime.h>
#include <cstddef>

#define BB   16
#define NN   8192
#define SS   1024        // NPOINT
#define KK   32          // NSAMPLE
#define DD   9
#define NPT  (BB*NN)     // 131072 unique columns
#define MCOLD ((double)(BB*SS*KK))   // BN divisor = gathered count 524288
#define NBLKMAX 4096

// ---------------- device scratch (static) ----------------
__device__ float  g_Y1[(size_t)64  * NPT];
__device__ float  g_Y2T[(size_t)NPT * 128];   // column-major layer2 out
__device__ int    g_cent[BB * SS];
__device__ int    g_idx[BB * SS * KK];        // gathered column ids
__device__ int    g_cnt[NPT];                 // gather multiplicity
__device__ int    g_prog[BB];                 // fps progress per batch
__device__ double g_ps [(size_t)128 * NBLKMAX];
__device__ double g_pss[(size_t)128 * NBLKMAX];
__device__ float  g_scl[3][128];
__device__ float  g_shf[3][128];

// ---------------- f32x2 packed helpers (sm_100+) ----------------
__device__ __forceinline__ unsigned long long pack2(float a, float b) {
    unsigned long long r;
    asm("mov.b64 %0, {%1, %2};" : "=l"(r) : "f"(a), "f"(b));
    return r;
}
__device__ __forceinline__ void unpack2(unsigned long long v, float& a, float& b) {
    asm("mov.b64 {%0, %1}, %2;" : "=f"(a), "=f"(b) : "l"(v));
}
__device__ __forceinline__ unsigned long long fma2(unsigned long long a, unsigned long long b, unsigned long long c) {
    unsigned long long r;
    asm("fma.rn.f32x2 %0, %1, %2, %3;" : "=l"(r) : "l"(a), "l"(b), "l"(c));
    return r;
}

// spread 3 bits to positions 0,3,6
__device__ __forceinline__ unsigned x3bits(unsigned v) {
    return (v & 1u) | ((v & 2u) << 2) | ((v & 4u) << 4);
}

// ================= role: FPS with octree-pruned updates (bids 0..15) =================
// Exactness: skipped threads provably see d > Dst for all their points (triangle
// inequality with >=1e-3 relative margin vs <=1e-6 fp error), so Dst, the cached
// per-thread (max, min-orig-idx, coords) and hence the argmax are bit-identical
// to the full scan. Update path uses the R2-exact fma-chain distance formula and
// explicit first-original-index tie rule.
__device__ __forceinline__ void fps_role(const float* __restrict__ xyz, float* sh, int b)
{
    float* sxs = sh;                      // sorted coords
    float* sys = sh + NN;
    float* szs = sh + 2 * NN;
    unsigned* skey = (unsigned*)(sh + 3 * NN);   // sorted -> orig index
    __shared__ int hist[512];
    __shared__ unsigned bufv[2][32];
    __shared__ unsigned bufi[2][32];
    __shared__ float bufc[2][32][3];
    __shared__ float s_c0[3];

    int t = threadIdx.x;
    int lane = t & 31, w = t >> 5;
    const float* xb = xyz + (size_t)b * NN * 3;

    for (int i = t; i < 512; i += 1024) hist[i] = 0;
    __syncthreads();

    // load + cell id + rank (counting sort, morton 3bits/dim = 512 cells)
    float px[8], py[8], pz[8];
    unsigned cr[8];
#pragma unroll
    for (int j = 0; j < 8; j++) {
        int p = j * 1024 + t;
        px[j] = xb[p * 3 + 0];
        py[j] = xb[p * 3 + 1];
        pz[j] = xb[p * 3 + 2];
        unsigned qx = (unsigned)min(7, max(0, (int)(px[j] * 8.0f)));
        unsigned qy = (unsigned)min(7, max(0, (int)(py[j] * 8.0f)));
        unsigned qz = (unsigned)min(7, max(0, (int)(pz[j] * 8.0f)));
        unsigned cell = x3bits(qx) | (x3bits(qy) << 1) | (x3bits(qz) << 2);
        unsigned rank = (unsigned)atomicAdd(&hist[cell], 1);
        cr[j] = (cell << 13) | rank;
    }
    __syncthreads();
    // inclusive scan of hist[0..511]
    for (int off = 1; off < 512; off <<= 1) {
        int v = 0;
        if (t < 512 && t >= off) v = hist[t - off];
        __syncthreads();
        if (t < 512) hist[t] += v;
        __syncthreads();
    }
    // scatter into sorted order (any permutation is correctness-neutral)
#pragma unroll
    for (int j = 0; j < 8; j++) {
        unsigned cell = cr[j] >> 13, rank = cr[j] & 8191u;
        int pos = (cell ? hist[cell - 1] : 0) + (int)rank;
        sxs[pos] = px[j]; sys[pos] = py[j]; szs[pos] = pz[j];
        skey[pos] = (unsigned)(j * 1024 + t);
    }
    if (t == 0) g_cent[b * SS] = 0;
    __syncthreads();

    // per-thread bounding ball over slots [8t, 8t+8)
    int base = t * 8;
    float bcx, bcy, bcz, r;
    {
        float mnx = 3e38f, mxx = -3e38f, mny = 3e38f, mxy = -3e38f, mnz = 3e38f, mxz = -3e38f;
#pragma unroll
        for (int q = 0; q < 8; q++) {
            float x = sxs[base + q], y = sys[base + q], z = szs[base + q];
            mnx = fminf(mnx, x); mxx = fmaxf(mxx, x);
            mny = fminf(mny, y); mxy = fmaxf(mxy, y);
            mnz = fminf(mnz, z); mxz = fmaxf(mxz, z);
        }
        bcx = (mnx + mxx) * 0.5f; bcy = (mny + mxy) * 0.5f; bcz = (mnz + mxz) * 0.5f;
        float r2 = 0.0f;
#pragma unroll
        for (int q = 0; q < 8; q++) {
            float dx = sxs[base + q] - bcx, dy = sys[base + q] - bcy, dz = szs[base + q] - bcz;
            r2 = fmaxf(r2, dx * dx + dy * dy + dz * dz);
        }
        r = sqrtf(r2) * 1.001f + 1e-6f;
        // locate original point 0 (first centroid)
#pragma unroll
        for (int q = 0; q < 8; q++)
            if (skey[base + q] == 0u) {
                s_c0[0] = sxs[base + q]; s_c0[1] = sys[base + q]; s_c0[2] = szs[base + q];
            }
    }
    float Dst[8];
#pragma unroll
    for (int q = 0; q < 8; q++) Dst[q] = 1e10f;
    float lmax = -1.0f, wx = 0.0f, wy = 0.0f, wz = 0.0f, sm_t = 3.4e38f;
    unsigned lidx = 0xffffffffu;
    __syncthreads();
    float cx = s_c0[0], cy = s_c0[1], cz = s_c0[2];
    int par = 0;

    for (int it = 1; it < SS; ++it) {
        float ddx = __fsub_rn(bcx, cx), ddy = __fsub_rn(bcy, cy), ddz = __fsub_rn(bcz, cz);
        float dc2 = fmaf(ddz, ddz, fmaf(ddy, ddy, __fmul_rn(ddx, ddx)));
        if (dc2 <= sm_t) {
            // full update of this thread's 8 points (exact formula, exact tie rule)
            const float4* X4 = (const float4*)(sxs + base);
            const float4* Y4 = (const float4*)(sys + base);
            const float4* Z4 = (const float4*)(szs + base);
            const uint4*  K4 = (const uint4*)(skey + base);
            float4 xa = X4[0], xb4 = X4[1];
            float4 ya = Y4[0], yb4 = Y4[1];
            float4 za = Z4[0], zb4 = Z4[1];
            uint4  ka = K4[0], kb4 = K4[1];
            float X[8] = {xa.x, xa.y, xa.z, xa.w, xb4.x, xb4.y, xb4.z, xb4.w};
            float Yv[8] = {ya.x, ya.y, ya.z, ya.w, yb4.x, yb4.y, yb4.z, yb4.w};
            float Z[8] = {za.x, za.y, za.z, za.w, zb4.x, zb4.y, zb4.z, zb4.w};
            unsigned IL[8] = {ka.x, ka.y, ka.z, ka.w, kb4.x, kb4.y, kb4.z, kb4.w};
            float bv = -1.0f; unsigned bi = 0xffffffffu;
            float nx = 0.0f, ny = 0.0f, nz = 0.0f;
#pragma unroll
            for (int q = 0; q < 8; q++) {
                float dx = __fsub_rn(X[q], cx);
                float dy = __fsub_rn(Yv[q], cy);
                float dz = __fsub_rn(Z[q], cz);
                float d  = fmaf(dz, dz, fmaf(dy, dy, __fmul_rn(dx, dx)));
                float nd = fminf(Dst[q], d);
                Dst[q] = nd;
                bool bet = (nd > bv) || (nd == bv && IL[q] < bi);
                if (bet) { bv = nd; bi = IL[q]; nx = X[q]; ny = Yv[q]; nz = Z[q]; }
            }
            lmax = bv; lidx = bi; wx = nx; wy = ny; wz = nz;
            float th = fmaf(sqrtf(bv), 1.002f, r);
            sm_t = th * th;
        }
        // warp reduce on cached (lmax, min-orig-idx); winner lane publishes coords
        unsigned vb = __float_as_uint(lmax);
        unsigned m1 = __reduce_max_sync(0xffffffffu, vb);
        unsigned c1 = (vb == m1) ? lidx : 0xffffffffu;
        unsigned i1 = __reduce_min_sync(0xffffffffu, c1);
        if (vb == m1 && lidx == i1) {
            bufv[par][w] = m1; bufi[par][w] = i1;
            bufc[par][w][0] = wx; bufc[par][w][1] = wy; bufc[par][w][2] = wz;
        }
        __syncthreads();
        unsigned v2 = bufv[par][lane], i2 = bufi[par][lane];
        unsigned m2 = __reduce_max_sync(0xffffffffu, v2);
        unsigned c2 = (v2 == m2) ? i2 : 0xffffffffu;
        unsigned fari = __reduce_min_sync(0xffffffffu, c2);
        unsigned wmask = __ballot_sync(0xffffffffu, (v2 == m2) && (i2 == fari));
        int ws = __ffs(wmask) - 1;
        cx = bufc[par][ws][0]; cy = bufc[par][ws][1]; cz = bufc[par][ws][2];
        if (t == 0) {
            g_cent[b * SS + it] = (int)fari;
            if ((it & 31) == 31) { __threadfence(); atomicExch(&g_prog[b], it); }
        }
        par ^= 1;
    }
}

// ================= role: ball query (bids 16..527) — spin on fps progress =================
__device__ __forceinline__ void bq_role(const float* __restrict__ xyz,
                                        float* __restrict__ out_newxyz,
                                        float4* sp, int idx)
{
    int g = idx >> 4, b = idx & 15;
    int t = threadIdx.x, warp = t >> 5, lane = t & 31;
    int s = (g << 5) + warp;

    if (t == 0) {
        while (atomicAdd(&g_prog[b], 0) < (g << 5) + 31) __nanosleep(256);
        __threadfence();
    }
    __syncthreads();

    int cidx = g_cent[b * SS + s];
    const float* cp = xyz + ((size_t)b * NN + cidx) * 3;
    float cx = cp[0], cy = cp[1], cz = cp[2];
    float cn2 = fmaf(cz, cz, fmaf(cy, cy, __fmul_rn(cx, cx)));
    if (lane < 3) out_newxyz[(b * SS + s) * 3 + lane] = cp[lane];

    const float R2 = 0.04f;
    float dl = 3.4e38f;
    int   il = 0;

    for (int tile = 0; tile < 4; ++tile) {
        __syncthreads();
        for (int i = t; i < 2048; i += 1024) {
            int gp = tile * 2048 + i;
            const float* pp = xyz + ((size_t)b * NN + gp) * 3;
            float px = pp[0], py = pp[1], pz = pp[2];
            sp[i] = make_float4(px, py, pz, fmaf(pz, pz, fmaf(py, py, __fmul_rn(px, px))));
        }
        __syncthreads();
        for (int chunk = 0; chunk < 64; ++chunk) {
            float4 p = sp[chunk * 32 + lane];
            float dot = fmaf(cz, p.z, fmaf(cy, p.y, __fmul_rn(cx, p.x)));
            float d   = __fsub_rn(__fadd_rn(cn2, p.w), __fmul_rn(2.0f, dot));
            float d31 = __shfl_sync(0xffffffffu, dl, 31);
            unsigned mask = __ballot_sync(0xffffffffu, d <= R2 && d < d31);
            while (mask) {
                int c0 = __ffs(mask) - 1;
                mask &= mask - 1;
                float dc = __shfl_sync(0xffffffffu, d, c0);
                d31 = __shfl_sync(0xffffffffu, dl, 31);
                if (dc < d31) {
                    int pos = __popc(__ballot_sync(0xffffffffu, dl <= dc));
                    float dprev = __shfl_up_sync(0xffffffffu, dl, 1);
                    int   iprev = __shfl_up_sync(0xffffffffu, il, 1);
                    int ic = tile * 2048 + chunk * 32 + c0;
                    if (lane >= pos) {
                        dl = (lane == pos) ? dc : dprev;
                        il = (lane == pos) ? ic : iprev;
                    }
                }
            }
        }
    }

    int first = __shfl_sync(0xffffffffu, il, 0);
    int gi = (dl > R2) ? first : il;
    int col = b * NN + gi;
    g_idx[(b * SS + s) * KK + lane] = col;
    atomicAdd(&g_cnt[col], 1);
}

// ================= fused pipeline kernel =================
__global__ __launch_bounds__(1024, 1) void fused_kernel(const float* __restrict__ xyz,
                                                        float* __restrict__ out_newxyz)
{
    extern __shared__ float sh[];
    int bid = blockIdx.x;
    if (bid < 16) fps_role(xyz, sh, bid);
    else          bq_role(xyz, out_newxyz, reinterpret_cast<float4*>(sh), bid - 16);
}

// ---------------- layer0 input moments: S (9) + M2 upper triangle (45) ----------------
__global__ __launch_bounds__(256) void moments0_kernel(const float* __restrict__ points)
{
    __shared__ float swm[8][54];
    int t = threadIdx.x, lane = t & 31, warp = t >> 5;
    int base = blockIdx.x * 2048;

    float v[54];
#pragma unroll
    for (int i = 0; i < 54; i++) v[i] = 0.0f;

    for (int i = 0; i < 8; i++) {
        int col = base + i * 256 + t;
        float c = (float)g_cnt[col];
        float x[9];
#pragma unroll
        for (int k = 0; k < 9; k++) x[k] = points[(size_t)col * 9 + k];
        int idx = 9;
#pragma unroll
        for (int j = 0; j < 9; j++) {
            float cxx = c * x[j];
            v[j] = fmaf(c, x[j], v[j]);
#pragma unroll
            for (int l = j; l < 9; l++) { v[idx] = fmaf(cxx, x[l], v[idx]); idx++; }
        }
    }
#pragma unroll
    for (int i = 0; i < 54; i++) {
#pragma unroll
        for (int o = 16; o > 0; o >>= 1) v[i] += __shfl_xor_sync(0xffffffffu, v[i], o);
    }
    if (lane == 0) {
#pragma unroll
        for (int i = 0; i < 54; i++) swm[warp][i] = v[i];
    }
    __syncthreads();
    if (t < 54) {
        double a = 0.0;
#pragma unroll
        for (int wv = 0; wv < 8; wv++) a += (double)swm[wv][t];
        g_ps[(size_t)t * NBLKMAX + blockIdx.x] = a;
    }
}

// ---------------- BN0 finalize from moments (closed form, affine layer) ----------------
__global__ __launch_bounds__(64) void finalize0m_kernel(const float* __restrict__ W0,
                                                        const float* __restrict__ b0,
                                                        const float* __restrict__ gamma,
                                                        const float* __restrict__ beta)
{
    __shared__ double Sm[54];
    int t = threadIdx.x;
    if (t < 54) {
        double a = 0.0;
        for (int i = 0; i < 64; i++) a += g_ps[(size_t)t * NBLKMAX + i];
        Sm[t] = a;
    }
    __syncthreads();
    double w[9];
#pragma unroll
    for (int j = 0; j < 9; j++) w[j] = (double)W0[t * 9 + j];
    double b = (double)b0[t];
    double S1 = 0.0;
#pragma unroll
    for (int j = 0; j < 9; j++) S1 += w[j] * Sm[j];
    double sum = S1 + b * MCOLD;
    double Q = 0.0;
    int idx = 9;
#pragma unroll
    for (int j = 0; j < 9; j++)
#pragma unroll
        for (int l = j; l < 9; l++) {
            Q += ((j == l) ? 1.0 : 2.0) * w[j] * w[l] * Sm[idx];
            idx++;
        }
    Q += 2.0 * b * S1 + b * b * MCOLD;
    double mean = sum / MCOLD;
    double var  = Q / MCOLD - mean * mean;
    float sc = gamma[t] * rsqrtf((float)var + 1e-5f);
    g_scl[0][t] = sc;
    g_shf[0][t] = beta[t] - (float)mean * sc;
}

// ---------------- gemm1: layer0 recomputed in-register + layer1 GEMM ----------------
__global__ __launch_bounds__(256) void gemm1_kernel(const float* __restrict__ points,
                                                    float* __restrict__ Y,
                                                    const float* __restrict__ W0,
                                                    const float* __restrict__ b0,
                                                    const float* __restrict__ W1,
                                                    const float* __restrict__ Bv)
{
    constexpr int CIN = 64, COUT = 64, RW = 8;
    extern __shared__ float sm[];
    float* WsT  = sm;                    // [64][64]
    float* Xs   = sm + 4096;             // [64][128]
    float* sW0  = sm + 4096 + 8192;      // [576]
    float* sB0  = sW0 + 576;             // [64]
    float* scnt = sB0 + 64;              // [128]

    int t = threadIdx.x;
    int cg = t & 31, rg = t >> 5;
    size_t col0 = (size_t)blockIdx.x * 128;

    for (int i = t; i < CIN * COUT; i += 256) {
        int k = i / COUT, r = i - k * COUT;
        WsT[i] = W1[r * CIN + k];
    }
    for (int i = t; i < 576; i += 256) sW0[i] = W0[i];
    if (t < 64) sB0[t] = b0[t];
    if (t < 128) scnt[t] = (float)g_cnt[col0 + t];
    __syncthreads();

    {
        int col = t >> 1, sub = t & 1;
        const float* px = points + (col0 + col) * DD;
        float x[DD];
#pragma unroll
        for (int k = 0; k < DD; k++) x[k] = px[k];
        int r0 = sub * 32;
#pragma unroll 8
        for (int rr = 0; rr < 32; rr++) {
            int r = r0 + rr;
            float acc = 0.0f;
#pragma unroll
            for (int k = 0; k < DD; k++) acc = fmaf(sW0[r * DD + k], x[k], acc);
            float y = acc + sB0[r];
            Xs[r * 128 + col] = fmaxf(fmaf(g_scl[0][r], y, g_shf[0][r]), 0.0f);
        }
    }
    __syncthreads();

    unsigned long long acc[RW][2];
#pragma unroll
    for (int r = 0; r < RW; r++) { acc[r][0] = 0ull; acc[r][1] = 0ull; }

    const unsigned long long* Xs64 = reinterpret_cast<const unsigned long long*>(Xs);
    const float4* W4 = reinterpret_cast<const float4*>(WsT);
#pragma unroll 8
    for (int k = 0; k < CIN; k++) {
        unsigned long long x0 = Xs64[k * 64 + cg];
        unsigned long long x1 = Xs64[k * 64 + cg + 32];
#pragma unroll
        for (int q = 0; q < RW / 4; q++) {
            float4 wv = W4[k * (COUT / 4) + rg * (RW / 4) + q];
            float wa[4] = {wv.x, wv.y, wv.z, wv.w};
#pragma unroll
            for (int m = 0; m < 4; m++) {
                unsigned long long w2 = pack2(wa[m], wa[m]);
                acc[q * 4 + m][0] = fma2(w2, x0, acc[q * 4 + m][0]);
                acc[q * 4 + m][1] = fma2(w2, x1, acc[q * 4 + m][1]);
            }
        }
    }

    float c0 = scnt[2 * cg], c1 = scnt[2 * cg + 1];
    float c2 = scnt[2 * cg + 64], c3 = scnt[2 * cg + 65];
#pragma unroll
    for (int rr = 0; rr < RW; rr++) {
        int r = rg * RW + rr;
        float bb = Bv[r];
        float ya, yb, yc, yd;
        unpack2(acc[rr][0], ya, yb); ya += bb; yb += bb;
        unpack2(acc[rr][1], yc, yd); yc += bb; yd += bb;
        *reinterpret_cast<float2*>(Y + (size_t)r * NPT + col0 + 2 * cg)      = make_float2(ya, yb);
        *reinterpret_cast<float2*>(Y + (size_t)r * NPT + col0 + 64 + 2 * cg) = make_float2(yc, yd);
        float ps = fmaf(c0, ya, fmaf(c1, yb, fmaf(c2, yc, c3 * yd)));
        float pq = fmaf(c0, ya * ya, fmaf(c1, yb * yb, fmaf(c2, yc * yc, c3 * (yd * yd))));
#pragma unroll
        for (int o = 16; o > 0; o >>= 1) {
            ps += __shfl_xor_sync(0xffffffffu, ps, o);
            pq += __shfl_xor_sync(0xffffffffu, pq, o);
        }
        if (cg == 0) {
            g_ps [(size_t)r * NBLKMAX + blockIdx.x] = (double)ps;
            g_pss[(size_t)r * NBLKMAX + blockIdx.x] = (double)pq;
        }
    }
}

// ---------------- gemm2: warp-uniform-W, shfl stats, smem transpose ----------------
__global__ __launch_bounds__(256) void gemm2_kernel(const float* __restrict__ X,
                                                    float* __restrict__ Y,
                                                    const float* __restrict__ W,
                                                    const float* __restrict__ Bv)
{
    constexpr int CIN = 64, COUT = 128, RW = 16;
    extern __shared__ float sm[];
    float* WsT  = sm;
    float* Xs   = sm + CIN * COUT;
    float* scnt = sm + 128 * 134;

    int t = threadIdx.x;
    int cg = t & 31, rg = t >> 5;
    size_t col0 = (size_t)blockIdx.x * 128;

    for (int i = t; i < CIN * COUT; i += 256) {
        int k = i / COUT, r = i - k * COUT;
        WsT[i] = W[r * CIN + k];
    }
    for (int i = t; i < CIN * 128; i += 256) {
        int c = i >> 7, x = i & 127;
        float v = X[(size_t)c * NPT + col0 + x];
        v = fmaxf(fmaf(g_scl[1][c], v, g_shf[1][c]), 0.0f);
        Xs[i] = v;
    }
    if (t < 128) scnt[t] = (float)g_cnt[col0 + t];
    __syncthreads();

    unsigned long long acc[RW][2];
#pragma unroll
    for (int r = 0; r < RW; r++) { acc[r][0] = 0ull; acc[r][1] = 0ull; }

    const unsigned long long* Xs64 = reinterpret_cast<const unsigned long long*>(Xs);
    const float4* W4 = reinterpret_cast<const float4*>(WsT);
#pragma unroll 8
    for (int k = 0; k < CIN; k++) {
        unsigned long long x0 = Xs64[k * 64 + cg];
        unsigned long long x1 = Xs64[k * 64 + cg + 32];
#pragma unroll
        for (int q = 0; q < RW / 4; q++) {
            float4 wv = W4[k * (COUT / 4) + rg * (RW / 4) + q];
            float wa[4] = {wv.x, wv.y, wv.z, wv.w};
#pragma unroll
            for (int m = 0; m < 4; m++) {
                unsigned long long w2 = pack2(wa[m], wa[m]);
                acc[q * 4 + m][0] = fma2(w2, x0, acc[q * 4 + m][0]);
                acc[q * 4 + m][1] = fma2(w2, x1, acc[q * 4 + m][1]);
            }
        }
    }

    __syncthreads();

    float c0 = scnt[2 * cg], c1 = scnt[2 * cg + 1];
    float c2 = scnt[2 * cg + 64], c3 = scnt[2 * cg + 65];
#pragma unroll
    for (int rr = 0; rr < RW; rr++) {
        int r = rg * RW + rr;
        float bb = Bv[r];
        float ya, yb, yc, yd;
        unpack2(acc[rr][0], ya, yb); ya += bb; yb += bb;
        unpack2(acc[rr][1], yc, yd); yc += bb; yd += bb;
        *reinterpret_cast<float2*>(sm + r * 134 + 2 * cg)      = make_float2(ya, yb);
        *reinterpret_cast<float2*>(sm + r * 134 + 64 + 2 * cg) = make_float2(yc, yd);
        float ps = fmaf(c0, ya, fmaf(c1, yb, fmaf(c2, yc, c3 * yd)));
        float pq = fmaf(c0, ya * ya, fmaf(c1, yb * yb, fmaf(c2, yc * yc, c3 * (yd * yd))));
#pragma unroll
        for (int o = 16; o > 0; o >>= 1) {
            ps += __shfl_xor_sync(0xffffffffu, ps, o);
            pq += __shfl_xor_sync(0xffffffffu, pq, o);
        }
        if (cg == 0) {
            g_ps [(size_t)r * NBLKMAX + blockIdx.x] = (double)ps;
            g_pss[(size_t)r * NBLKMAX + blockIdx.x] = (double)pq;
        }
    }
    __syncthreads();
    float* tb = sm;
    float* yout = Y + col0 * 128;
#pragma unroll 8
    for (int i = 0; i < 64; i++) {
        int e = i * 256 + t;
        yout[e] = tb[(e & 127) * 134 + (e >> 7)];
    }
}

// ---------------- BN finalize (layers 1/2) ----------------
__global__ __launch_bounds__(128) void finalize_kernel(const float* __restrict__ gamma,
                                                       const float* __restrict__ beta,
                                                       int layer, int nblk)
{
    int c = blockIdx.x, t = threadIdx.x;
    __shared__ double sh1[128], sh2[128];
    double a = 0.0, q = 0.0;
    for (int i = t; i < nblk; i += 128) {
        a += g_ps [(size_t)c * NBLKMAX + i];
        q += g_pss[(size_t)c * NBLKMAX + i];
    }
    sh1[t] = a; sh2[t] = q;
    __syncthreads();
    for (int o = 64; o > 0; o >>= 1) {
        if (t < o) { sh1[t] += sh1[t + o]; sh2[t] += sh2[t + o]; }
        __syncthreads();
    }
    if (t == 0) {
        double mean = sh1[0] / MCOLD;
        double var  = sh2[0] / MCOLD - mean * mean;
        float sc = gamma[c] * rsqrtf((float)var + 1e-5f);
        g_scl[layer][c] = sc;
        g_shf[layer][c] = beta[c] - (float)mean * sc;
    }
}

// ---------------- final: gather-max + BN2 affine + relu; also resets cnt/prog ---------
__global__ __launch_bounds__(256) void final_kernel(float* __restrict__ out)
{
    int warp = threadIdx.x >> 5, lane = threadIdx.x & 31;
    int cent = blockIdx.x * 8 + warp;
    int myidx = g_idx[cent * KK + lane];
    float4 mx = make_float4(-3.4e38f, -3.4e38f, -3.4e38f, -3.4e38f);
#pragma unroll
    for (int j = 0; j < KK; j++) {
        int col = __shfl_sync(0xffffffffu, myidx, j);
        float4 v = *reinterpret_cast<const float4*>(g_Y2T + (size_t)col * 128 + lane * 4);
        mx.x = fmaxf(mx.x, v.x);
        mx.y = fmaxf(mx.y, v.y);
        mx.z = fmaxf(mx.z, v.z);
        mx.w = fmaxf(mx.w, v.w);
    }
    int c0 = lane * 4;
    float4 o;
    o.x = fmaxf(fmaf(g_scl[2][c0 + 0], mx.x, g_shf[2][c0 + 0]), 0.0f);
    o.y = fmaxf(fmaf(g_scl[2][c0 + 1], mx.y, g_shf[2][c0 + 1]), 0.0f);
    o.z = fmaxf(fmaf(g_scl[2][c0 + 2], mx.z, g_shf[2][c0 + 2]), 0.0f);
    o.w = fmaxf(fmaf(g_scl[2][c0 + 3], mx.w, g_shf[2][c0 + 3]), 0.0f);
    *reinterpret_cast<float4*>(out + (size_t)cent * 128 + c0) = o;

    // merged reset: leave counts/progress clean for the next call / graph replay
    int gid = blockIdx.x * 256 + threadIdx.x;
    if (gid < NPT) g_cnt[gid] = 0;
    if (gid < BB) g_prog[gid] = 0;
}

// ---------------- launch ----------------
extern "C" void kernel_launch(void* const* d_in, const int* in_sizes, int n_in,
                              void* d_out, int out_size)
{
    const float* xyz    = (const float*)d_in[0];
    const float* points = (const float*)d_in[1];
    const float* W0 = (const float*)d_in[2];
    const float* b0 = (const float*)d_in[3];
    const float* g0 = (const float*)d_in[4];
    const float* be0 = (const float*)d_in[5];
    const float* W1 = (const float*)d_in[6];
    const float* b1 = (const float*)d_in[7];
    const float* g1 = (const float*)d_in[8];
    const float* be1 = (const float*)d_in[9];
    const float* W2 = (const float*)d_in[10];
    const float* b2 = (const float*)d_in[11];
    const float* g2 = (const float*)d_in[12];
    const float* be2 = (const float*)d_in[13];

    float* out      = (float*)d_out;
    float* out_feat = out + BB * SS * 3;

    float *pY1, *pY2T;
    cudaGetSymbolAddress((void**)&pY1, g_Y1);
    cudaGetSymbolAddress((void**)&pY2T, g_Y2T);

    // launch order: fused(1), moments0(2), fin0m(3), gemm1(4 = ncu slot), ...
    // cnt/prog are zero at entry (zero-init on load; final_kernel resets each call).

    // fused fps(sorted+pruned) + ballquery pipeline (128KB smem)
    const int FUSED_SMEM = 32 * NN * 4 / 8 * 4;   // 4*NN floats = 128KB
    cudaFuncSetAttribute(fused_kernel, cudaFuncAttributeMaxDynamicSharedMemorySize, 4 * NN * 4);
    fused_kernel<<<16 + 512, 1024, 4 * NN * 4>>>(xyz, out);
    (void)FUSED_SMEM;

    // BN0 stats from input moments (closed form: layer0 is affine)
    moments0_kernel<<<64, 256>>>(points);
    finalize0m_kernel<<<1, 64>>>(W0, b0, g0, be0);

    // layer 0+1 fused
    {
        size_t smem = (size_t)(4096 + 8192 + 576 + 64 + 128) * 4;
        cudaFuncSetAttribute(gemm1_kernel, cudaFuncAttributeMaxDynamicSharedMemorySize, (int)smem);
        gemm1_kernel<<<NPT / 128, 256, smem>>>(points, pY1, W0, b0, W1, b1);
        finalize_kernel<<<64, 128>>>(g1, be1, 1, NPT / 128);
    }
    // layer 2
    {
        size_t smem = (size_t)(128 * 134 + 128) * 4;
        cudaFuncSetAttribute(gemm2_kernel, cudaFuncAttributeMaxDynamicSharedMemorySize, (int)smem);
        gemm2_kernel<<<NPT / 128, 256, smem>>>(pY1, pY2T, W2, b2);
        finalize_kernel<<<128, 128>>>(g2, be2, 2, NPT / 128);
    }
    // gather-max + BN2 + relu -> feature output (+ state reset)
    final_kernel<<<(BB * SS) / 8, 256>>>(out_feat);
}

// round 17
// speedup vs baseline: 1.2604x; 1.2604x over previous
#include <cuda_runtime.h>
#include <cstddef>

#define BB   16
#define NN   8192
#define SS   1024        // NPOINT
#define KK   32          // NSAMPLE
#define DD   9
#define NPT  (BB*NN)     // 131072 unique columns
#define MCOLD ((double)(BB*SS*KK))   // BN divisor = gathered count 524288
#define NBLKMAX 4096

// ---------------- device scratch (static) ----------------
__device__ float  g_Y1[(size_t)64  * NPT];
__device__ float  g_Y2T[(size_t)NPT * 128];   // column-major layer2 out
__device__ int    g_cent[BB * SS];
__device__ int    g_idx[BB * SS * KK];        // gathered column ids
__device__ int    g_cnt[NPT];                 // gather multiplicity
__device__ int    g_prog[BB];                 // fps progress per batch
__device__ double g_ps [(size_t)128 * NBLKMAX];
__device__ double g_pss[(size_t)128 * NBLKMAX];
__device__ float  g_scl[3][128];
__device__ float  g_shf[3][128];

// ---------------- f32x2 packed helpers (sm_100+) ----------------
__device__ __forceinline__ unsigned long long pack2(float a, float b) {
    unsigned long long r;
    asm("mov.b64 %0, {%1, %2};" : "=l"(r) : "f"(a), "f"(b));
    return r;
}
__device__ __forceinline__ void unpack2(unsigned long long v, float& a, float& b) {
    asm("mov.b64 {%0, %1}, %2;" : "=f"(a), "=f"(b) : "l"(v));
}
__device__ __forceinline__ unsigned long long add2(unsigned long long a, unsigned long long b) {
    unsigned long long r;
    asm("add.rn.f32x2 %0, %1, %2;" : "=l"(r) : "l"(a), "l"(b));
    return r;
}
__device__ __forceinline__ unsigned long long mul2(unsigned long long a, unsigned long long b) {
    unsigned long long r;
    asm("mul.rn.f32x2 %0, %1, %2;" : "=l"(r) : "l"(a), "l"(b));
    return r;
}
__device__ __forceinline__ unsigned long long fma2(unsigned long long a, unsigned long long b, unsigned long long c) {
    unsigned long long r;
    asm("fma.rn.f32x2 %0, %1, %2, %3;" : "=l"(r) : "l"(a), "l"(b), "l"(c));
    return r;
}

// ---------------- reset ----------------
__global__ void reset_kernel() {
    int i = blockIdx.x * 256 + threadIdx.x;
    g_cnt[i] = 0;
    if (i < BB) g_prog[i] = 0;
}

// ================= role: FPS (bids 0..15) — R12/R14/R15-exact =================
__device__ __forceinline__ void fps_role(const float* __restrict__ xyz, float* sh, int b)
{
    float* sx = sh;
    float* sy = sh + NN;
    float* sz = sh + 2 * NN;
    __shared__ unsigned bufv[2][32];
    __shared__ unsigned bufi[2][32];

    int t = threadIdx.x;
    int lane = t & 31, w = t >> 5;
    const float* xb = xyz + (size_t)b * NN * 3;

    float xs[8], ys[8], zs[8], Dst[8];
#pragma unroll
    for (int j = 0; j < 8; j++) {
        int p = j * 1024 + t;
        xs[j] = xb[p * 3 + 0];
        ys[j] = xb[p * 3 + 1];
        zs[j] = xb[p * 3 + 2];
        Dst[j] = 1e10f;
        sx[p] = xs[j]; sy[p] = ys[j]; sz[p] = zs[j];
    }
    unsigned long long X2[4], Y2[4], Z2[4];
#pragma unroll
    for (int jp = 0; jp < 4; jp++) {
        X2[jp] = pack2(xs[2 * jp], xs[2 * jp + 1]);
        Y2[jp] = pack2(ys[2 * jp], ys[2 * jp + 1]);
        Z2[jp] = pack2(zs[2 * jp], zs[2 * jp + 1]);
    }
    if (t == 0) g_cent[b * SS] = 0;
    int far = 0, par = 0;
    __syncthreads();

    for (int it = 1; it < SS; ++it) {
        float cx = sx[far], cy = sy[far], cz = sz[far];
        unsigned long long cx2 = pack2(-cx, -cx);
        unsigned long long cy2 = pack2(-cy, -cy);
        unsigned long long cz2 = pack2(-cz, -cz);
        float bv = -1.0f; int bi = 0;
#pragma unroll
        for (int jp = 0; jp < 4; jp++) {
            unsigned long long dx2 = add2(X2[jp], cx2);
            unsigned long long dy2 = add2(Y2[jp], cy2);
            unsigned long long dz2 = add2(Z2[jp], cz2);
            unsigned long long d2 = fma2(dz2, dz2, fma2(dy2, dy2, mul2(dx2, dx2)));
            float dlo, dhi;
            unpack2(d2, dlo, dhi);
            float nlo = fminf(Dst[2 * jp], dlo);
            float nhi = fminf(Dst[2 * jp + 1], dhi);
            Dst[2 * jp] = nlo;
            Dst[2 * jp + 1] = nhi;
            if (nlo > bv) { bv = nlo; bi = 2 * jp * 1024 + t; }
            if (nhi > bv) { bv = nhi; bi = (2 * jp + 1) * 1024 + t; }
        }
        unsigned vb = __float_as_uint(bv);
        unsigned m1 = __reduce_max_sync(0xffffffffu, vb);
        unsigned c1 = (vb == m1) ? (unsigned)bi : 0xffffffffu;
        unsigned i1 = __reduce_min_sync(0xffffffffu, c1);
        if (lane == 0) { bufv[par][w] = m1; bufi[par][w] = i1; }
        __syncthreads();
        unsigned v2 = bufv[par][lane];
        unsigned i2 = bufi[par][lane];
        unsigned m2 = __reduce_max_sync(0xffffffffu, v2);
        unsigned c2 = (v2 == m2) ? i2 : 0xffffffffu;
        far = (int)__reduce_min_sync(0xffffffffu, c2);
        if (t == 0) {
            g_cent[b * SS + it] = far;
            if ((it & 31) == 31) { __threadfence(); atomicExch(&g_prog[b], it); }
        }
        par ^= 1;
    }
}

// ================= role: ball query (bids 16..527) — spin on fps progress =================
__device__ __forceinline__ void bq_role(const float* __restrict__ xyz,
                                        float* __restrict__ out_newxyz,
                                        float4* sp, int idx)
{
    int g = idx >> 4, b = idx & 15;
    int t = threadIdx.x, warp = t >> 5, lane = t & 31;
    int s = (g << 5) + warp;

    if (t == 0) {
        while (atomicAdd(&g_prog[b], 0) < (g << 5) + 31) __nanosleep(256);
        __threadfence();
    }
    __syncthreads();

    int cidx = g_cent[b * SS + s];
    const float* cp = xyz + ((size_t)b * NN + cidx) * 3;
    float cx = cp[0], cy = cp[1], cz = cp[2];
    float cn2 = fmaf(cz, cz, fmaf(cy, cy, __fmul_rn(cx, cx)));
    if (lane < 3) out_newxyz[(b * SS + s) * 3 + lane] = cp[lane];

    const float R2 = 0.04f;
    float dl = 3.4e38f;
    int   il = 0;

    for (int tile = 0; tile < 4; ++tile) {
        __syncthreads();
        for (int i = t; i < 2048; i += 1024) {
            int gp = tile * 2048 + i;
            const float* pp = xyz + ((size_t)b * NN + gp) * 3;
            float px = pp[0], py = pp[1], pz = pp[2];
            sp[i] = make_float4(px, py, pz, fmaf(pz, pz, fmaf(py, py, __fmul_rn(px, px))));
        }
        __syncthreads();
        for (int chunk = 0; chunk < 64; ++chunk) {
            float4 p = sp[chunk * 32 + lane];
            float dot = fmaf(cz, p.z, fmaf(cy, p.y, __fmul_rn(cx, p.x)));
            float d   = __fsub_rn(__fadd_rn(cn2, p.w), __fmul_rn(2.0f, dot));
            float d31 = __shfl_sync(0xffffffffu, dl, 31);
            unsigned mask = __ballot_sync(0xffffffffu, d <= R2 && d < d31);
            while (mask) {
                int c0 = __ffs(mask) - 1;
                mask &= mask - 1;
                float dc = __shfl_sync(0xffffffffu, d, c0);
                d31 = __shfl_sync(0xffffffffu, dl, 31);
                if (dc < d31) {
                    int pos = __popc(__ballot_sync(0xffffffffu, dl <= dc));
                    float dprev = __shfl_up_sync(0xffffffffu, dl, 1);
                    int   iprev = __shfl_up_sync(0xffffffffu, il, 1);
                    int ic = tile * 2048 + chunk * 32 + c0;
                    if (lane >= pos) {
                        dl = (lane == pos) ? dc : dprev;
                        il = (lane == pos) ? ic : iprev;
                    }
                }
            }
        }
    }

    int first = __shfl_sync(0xffffffffu, il, 0);
    int gi = (dl > R2) ? first : il;
    int col = b * NN + gi;
    g_idx[(b * SS + s) * KK + lane] = col;
    atomicAdd(&g_cnt[col], 1);
}

// ================= fused pipeline kernel =================
__global__ __launch_bounds__(1024, 1) void fused_kernel(const float* __restrict__ xyz,
                                                        float* __restrict__ out_newxyz)
{
    extern __shared__ float sh[];
    int bid = blockIdx.x;
    if (bid < 16) fps_role(xyz, sh, bid);
    else          bq_role(xyz, out_newxyz, reinterpret_cast<float4*>(sh), bid - 16);
}

// ---------------- layer0 input moments: S (9) + M2 upper triangle (45) ----------------
// 256 blocks x 256 threads x 2 cols (higher grid parallelism for latency hiding).
__global__ __launch_bounds__(256) void moments0_kernel(const float* __restrict__ points)
{
    __shared__ float swm[8][54];
    int t = threadIdx.x, lane = t & 31, warp = t >> 5;
    int base = blockIdx.x * 512;

    float v[54];
#pragma unroll
    for (int i = 0; i < 54; i++) v[i] = 0.0f;

    for (int i = 0; i < 2; i++) {
        int col = base + i * 256 + t;
        float c = (float)g_cnt[col];
        float x[9];
#pragma unroll
        for (int k = 0; k < 9; k++) x[k] = points[(size_t)col * 9 + k];
        int idx = 9;
#pragma unroll
        for (int j = 0; j < 9; j++) {
            float cxx = c * x[j];
            v[j] = fmaf(c, x[j], v[j]);
#pragma unroll
            for (int l = j; l < 9; l++) { v[idx] = fmaf(cxx, x[l], v[idx]); idx++; }
        }
    }
#pragma unroll
    for (int i = 0; i < 54; i++) {
#pragma unroll
        for (int o = 16; o > 0; o >>= 1) v[i] += __shfl_xor_sync(0xffffffffu, v[i], o);
    }
    if (lane == 0) {
#pragma unroll
        for (int i = 0; i < 54; i++) swm[warp][i] = v[i];
    }
    __syncthreads();
    if (t < 54) {
        double a = 0.0;
#pragma unroll
        for (int wv = 0; wv < 8; wv++) a += (double)swm[wv][t];
        g_ps[(size_t)t * NBLKMAX + blockIdx.x] = a;
    }
}

// ---------------- BN0 finalize from moments (closed form, affine layer) ----------------
__global__ __launch_bounds__(64) void finalize0m_kernel(const float* __restrict__ W0,
                                                        const float* __restrict__ b0,
                                                        const float* __restrict__ gamma,
                                                        const float* __restrict__ beta)
{
    __shared__ double Sm[54];
    int t = threadIdx.x;
    if (t < 54) {
        double a = 0.0;
        for (int i = 0; i < 256; i++) a += g_ps[(size_t)t * NBLKMAX + i];
        Sm[t] = a;
    }
    __syncthreads();
    double w[9];
#pragma unroll
    for (int j = 0; j < 9; j++) w[j] = (double)W0[t * 9 + j];
    double b = (double)b0[t];
    double S1 = 0.0;
#pragma unroll
    for (int j = 0; j < 9; j++) S1 += w[j] * Sm[j];
    double sum = S1 + b * MCOLD;
    double Q = 0.0;
    int idx = 9;
#pragma unroll
    for (int j = 0; j < 9; j++)
#pragma unroll
        for (int l = j; l < 9; l++) {
            Q += ((j == l) ? 1.0 : 2.0) * w[j] * w[l] * Sm[idx];
            idx++;
        }
    Q += 2.0 * b * S1 + b * b * MCOLD;
    double mean = sum / MCOLD;
    double var  = Q / MCOLD - mean * mean;
    float sc = gamma[t] * rsqrtf((float)var + 1e-5f);
    g_scl[0][t] = sc;
    g_shf[0][t] = beta[t] - (float)mean * sc;
}

// ---------------- gemm1: layer0 recomputed in-register + layer1 GEMM ----------------
// Xs fill: col = t&127 (conflict-free STS: warp lanes hit 32 consecutive columns).
__global__ __launch_bounds__(256) void gemm1_kernel(const float* __restrict__ points,
                                                    float* __restrict__ Y,
                                                    const float* __restrict__ W0,
                                                    const float* __restrict__ b0,
                                                    const float* __restrict__ W1,
                                                    const float* __restrict__ Bv)
{
    constexpr int CIN = 64, COUT = 64, RW = 8;
    extern __shared__ float sm[];
    float* WsT  = sm;                    // [64][64]
    float* Xs   = sm + 4096;             // [64][128]
    float* sW0  = sm + 4096 + 8192;      // [576]
    float* sB0  = sW0 + 576;             // [64]
    float* scnt = sB0 + 64;              // [128]

    int t = threadIdx.x;
    int cg = t & 31, rg = t >> 5;
    size_t col0 = (size_t)blockIdx.x * 128;

    for (int i = t; i < CIN * COUT; i += 256) {
        int k = i / COUT, r = i - k * COUT;
        WsT[i] = W1[r * CIN + k];
    }
    for (int i = t; i < 576; i += 256) sW0[i] = W0[i];
    if (t < 64) sB0[t] = b0[t];
    if (t < 128) scnt[t] = (float)g_cnt[col0 + t];
    __syncthreads();

    // compute u for this block's 128 columns (2 threads per column, conflict-free)
    {
        int col = t & 127, sub = t >> 7;
        const float* px = points + (col0 + col) * DD;
        float x[DD];
#pragma unroll
        for (int k = 0; k < DD; k++) x[k] = px[k];
        int r0 = sub * 32;
#pragma unroll 8
        for (int rr = 0; rr < 32; rr++) {
            int r = r0 + rr;
            float acc = 0.0f;
#pragma unroll
            for (int k = 0; k < DD; k++) acc = fmaf(sW0[r * DD + k], x[k], acc);
            float y = acc + sB0[r];
            Xs[r * 128 + col] = fmaxf(fmaf(g_scl[0][r], y, g_shf[0][r]), 0.0f);
        }
    }
    __syncthreads();

    unsigned long long acc[RW][2];
#pragma unroll
    for (int r = 0; r < RW; r++) { acc[r][0] = 0ull; acc[r][1] = 0ull; }

    const unsigned long long* Xs64 = reinterpret_cast<const unsigned long long*>(Xs);
    const float4* W4 = reinterpret_cast<const float4*>(WsT);
#pragma unroll 8
    for (int k = 0; k < CIN; k++) {
        unsigned long long x0 = Xs64[k * 64 + cg];
        unsigned long long x1 = Xs64[k * 64 + cg + 32];
#pragma unroll
        for (int q = 0; q < RW / 4; q++) {
            float4 wv = W4[k * (COUT / 4) + rg * (RW / 4) + q];   // warp-uniform
            float wa[4] = {wv.x, wv.y, wv.z, wv.w};
#pragma unroll
            for (int m = 0; m < 4; m++) {
                unsigned long long w2 = pack2(wa[m], wa[m]);
                acc[q * 4 + m][0] = fma2(w2, x0, acc[q * 4 + m][0]);
                acc[q * 4 + m][1] = fma2(w2, x1, acc[q * 4 + m][1]);
            }
        }
    }

    float c0 = scnt[2 * cg], c1 = scnt[2 * cg + 1];
    float c2 = scnt[2 * cg + 64], c3 = scnt[2 * cg + 65];
#pragma unroll
    for (int rr = 0; rr < RW; rr++) {
        int r = rg * RW + rr;
        float bb = Bv[r];
        float ya, yb, yc, yd;
        unpack2(acc[rr][0], ya, yb); ya += bb; yb += bb;
        unpack2(acc[rr][1], yc, yd); yc += bb; yd += bb;
        *reinterpret_cast<float2*>(Y + (size_t)r * NPT + col0 + 2 * cg)      = make_float2(ya, yb);
        *reinterpret_cast<float2*>(Y + (size_t)r * NPT + col0 + 64 + 2 * cg) = make_float2(yc, yd);
        float ps = fmaf(c0, ya, fmaf(c1, yb, fmaf(c2, yc, c3 * yd)));
        float pq = fmaf(c0, ya * ya, fmaf(c1, yb * yb, fmaf(c2, yc * yc, c3 * (yd * yd))));
#pragma unroll
        for (int o = 16; o > 0; o >>= 1) {
            ps += __shfl_xor_sync(0xffffffffu, ps, o);
            pq += __shfl_xor_sync(0xffffffffu, pq, o);
        }
        if (cg == 0) {
            g_ps [(size_t)r * NBLKMAX + blockIdx.x] = (double)ps;
            g_pss[(size_t)r * NBLKMAX + blockIdx.x] = (double)pq;
        }
    }
}

// ---------------- gemm2: warp-uniform-W, shfl stats, smem transpose ----------------
__global__ __launch_bounds__(256) void gemm2_kernel(const float* __restrict__ X,
                                                    float* __restrict__ Y,
                                                    const float* __restrict__ W,
                                                    const float* __restrict__ Bv)
{
    constexpr int CIN = 64, COUT = 128, RW = 16;
    extern __shared__ float sm[];
    float* WsT  = sm;
    float* Xs   = sm + CIN * COUT;
    float* scnt = sm + 128 * 134;

    int t = threadIdx.x;
    int cg = t & 31, rg = t >> 5;
    size_t col0 = (size_t)blockIdx.x * 128;

    for (int i = t; i < CIN * COUT; i += 256) {
        int k = i / COUT, r = i - k * COUT;
        WsT[i] = W[r * CIN + k];
    }
    for (int i = t; i < CIN * 128; i += 256) {
        int c = i >> 7, x = i & 127;
        float v = X[(size_t)c * NPT + col0 + x];
        v = fmaxf(fmaf(g_scl[1][c], v, g_shf[1][c]), 0.0f);
        Xs[i] = v;
    }
    if (t < 128) scnt[t] = (float)g_cnt[col0 + t];
    __syncthreads();

    unsigned long long acc[RW][2];
#pragma unroll
    for (int r = 0; r < RW; r++) { acc[r][0] = 0ull; acc[r][1] = 0ull; }

    const unsigned long long* Xs64 = reinterpret_cast<const unsigned long long*>(Xs);
    const float4* W4 = reinterpret_cast<const float4*>(WsT);
#pragma unroll 8
    for (int k = 0; k < CIN; k++) {
        unsigned long long x0 = Xs64[k * 64 + cg];
        unsigned long long x1 = Xs64[k * 64 + cg + 32];
#pragma unroll
        for (int q = 0; q < RW / 4; q++) {
            float4 wv = W4[k * (COUT / 4) + rg * (RW / 4) + q];
            float wa[4] = {wv.x, wv.y, wv.z, wv.w};
#pragma unroll
            for (int m = 0; m < 4; m++) {
                unsigned long long w2 = pack2(wa[m], wa[m]);
                acc[q * 4 + m][0] = fma2(w2, x0, acc[q * 4 + m][0]);
                acc[q * 4 + m][1] = fma2(w2, x1, acc[q * 4 + m][1]);
            }
        }
    }

    __syncthreads();                     // tb aliases WsT/Xs

    float c0 = scnt[2 * cg], c1 = scnt[2 * cg + 1];
    float c2 = scnt[2 * cg + 64], c3 = scnt[2 * cg + 65];
#pragma unroll
    for (int rr = 0; rr < RW; rr++) {
        int r = rg * RW + rr;
        float bb = Bv[r];
        float ya, yb, yc, yd;
        unpack2(acc[rr][0], ya, yb); ya += bb; yb += bb;
        unpack2(acc[rr][1], yc, yd); yc += bb; yd += bb;
        *reinterpret_cast<float2*>(sm + r * 134 + 2 * cg)      = make_float2(ya, yb);
        *reinterpret_cast<float2*>(sm + r * 134 + 64 + 2 * cg) = make_float2(yc, yd);
        float ps = fmaf(c0, ya, fmaf(c1, yb, fmaf(c2, yc, c3 * yd)));
        float pq = fmaf(c0, ya * ya, fmaf(c1, yb * yb, fmaf(c2, yc * yc, c3 * (yd * yd))));
#pragma unroll
        for (int o = 16; o > 0; o >>= 1) {
            ps += __shfl_xor_sync(0xffffffffu, ps, o);
            pq += __shfl_xor_sync(0xffffffffu, pq, o);
        }
        if (cg == 0) {
            g_ps [(size_t)r * NBLKMAX + blockIdx.x] = (double)ps;
            g_pss[(size_t)r * NBLKMAX + blockIdx.x] = (double)pq;
        }
    }
    __syncthreads();
    float* tb = sm;
    float* yout = Y + col0 * 128;
#pragma unroll 8
    for (int i = 0; i < 64; i++) {
        int e = i * 256 + t;
        yout[e] = tb[(e & 127) * 134 + (e >> 7)];   // linear coalesced STG.32
    }
}

// ---------------- BN finalize (layers 1/2) ----------------
__global__ __launch_bounds__(128) void finalize_kernel(const float* __restrict__ gamma,
                                                       const float* __restrict__ beta,
                                                       int layer, int nblk)
{
    int c = blockIdx.x, t = threadIdx.x;
    __shared__ double sh1[128], sh2[128];
    double a = 0.0, q = 0.0;
    for (int i = t; i < nblk; i += 128) {
        a += g_ps [(size_t)c * NBLKMAX + i];
        q += g_pss[(size_t)c * NBLKMAX + i];
    }
    sh1[t] = a; sh2[t] = q;
    __syncthreads();
    for (int o = 64; o > 0; o >>= 1) {
        if (t < o) { sh1[t] += sh1[t + o]; sh2[t] += sh2[t + o]; }
        __syncthreads();
    }
    if (t == 0) {
        double mean = sh1[0] / MCOLD;
        double var  = sh2[0] / MCOLD - mean * mean;
        float sc = gamma[c] * rsqrtf((float)var + 1e-5f);
        g_scl[layer][c] = sc;
        g_shf[layer][c] = beta[c] - (float)mean * sc;
    }
}

// ---------------- final: gather-max over 32 idx cols + BN2 affine + relu ------------
__global__ __launch_bounds__(256) void final_kernel(float* __restrict__ out)
{
    int warp = threadIdx.x >> 5, lane = threadIdx.x & 31;
    int cent = blockIdx.x * 8 + warp;
    int myidx = g_idx[cent * KK + lane];
    float4 mx = make_float4(-3.4e38f, -3.4e38f, -3.4e38f, -3.4e38f);
#pragma unroll
    for (int j = 0; j < KK; j++) {
        int col = __shfl_sync(0xffffffffu, myidx, j);
        float4 v = *reinterpret_cast<const float4*>(g_Y2T + (size_t)col * 128 + lane * 4);
        mx.x = fmaxf(mx.x, v.x);
        mx.y = fmaxf(mx.y, v.y);
        mx.z = fmaxf(mx.z, v.z);
        mx.w = fmaxf(mx.w, v.w);
    }
    int c0 = lane * 4;
    float4 o;
    o.x = fmaxf(fmaf(g_scl[2][c0 + 0], mx.x, g_shf[2][c0 + 0]), 0.0f);
    o.y = fmaxf(fmaf(g_scl[2][c0 + 1], mx.y, g_shf[2][c0 + 1]), 0.0f);
    o.z = fmaxf(fmaf(g_scl[2][c0 + 2], mx.z, g_shf[2][c0 + 2]), 0.0f);
    o.w = fmaxf(fmaf(g_scl[2][c0 + 3], mx.w, g_shf[2][c0 + 3]), 0.0f);
    *reinterpret_cast<float4*>(out + (size_t)cent * 128 + c0) = o;
}

// ---------------- launch ----------------
extern "C" void kernel_launch(void* const* d_in, const int* in_sizes, int n_in,
                              void* d_out, int out_size)
{
    const float* xyz    = (const float*)d_in[0];
    const float* points = (const float*)d_in[1];
    const float* W0 = (const float*)d_in[2];
    const float* b0 = (const float*)d_in[3];
    const float* g0 = (const float*)d_in[4];
    const float* be0 = (const float*)d_in[5];
    const float* W1 = (const float*)d_in[6];
    const float* b1 = (const float*)d_in[7];
    const float* g1 = (const float*)d_in[8];
    const float* be1 = (const float*)d_in[9];
    const float* W2 = (const float*)d_in[10];
    const float* b2 = (const float*)d_in[11];
    const float* g2 = (const float*)d_in[12];
    const float* be2 = (const float*)d_in[13];

    float* out      = (float*)d_out;
    float* out_feat = out + BB * SS * 3;

    float *pY1, *pY2T;
    cudaGetSymbolAddress((void**)&pY1, g_Y1);
    cudaGetSymbolAddress((void**)&pY2T, g_Y2T);

    // reset counts + progress (fresh every graph replay)
    reset_kernel<<<NPT / 256, 256>>>();

    // fused fps + ballquery pipeline (96KB smem, 1 block/SM via regs)
    const int FUSED_SMEM = 3 * NN * 4;
    cudaFuncSetAttribute(fused_kernel, cudaFuncAttributeMaxDynamicSharedMemorySize, FUSED_SMEM);
    fused_kernel<<<16 + 512, 1024, FUSED_SMEM>>>(xyz, out);

    // BN0 stats from input moments (closed form: layer0 is affine)
    moments0_kernel<<<256, 256>>>(points);
    finalize0m_kernel<<<1, 64>>>(W0, b0, g0, be0);

    // layer 0+1 fused: recompute u in-register, 64->64 GEMM
    {
        size_t smem = (size_t)(4096 + 8192 + 576 + 64 + 128) * 4;
        cudaFuncSetAttribute(gemm1_kernel, cudaFuncAttributeMaxDynamicSharedMemorySize, (int)smem);
        gemm1_kernel<<<NPT / 128, 256, smem>>>(points, pY1, W0, b0, W1, b1);
        finalize_kernel<<<64, 128>>>(g1, be1, 1, NPT / 128);
    }
    // layer 2: 64 -> 128, column-major output via smem transpose
    {
        size_t smem = (size_t)(128 * 134 + 128) * 4;
        cudaFuncSetAttribute(gemm2_kernel, cudaFuncAttributeMaxDynamicSharedMemorySize, (int)smem);
        gemm2_kernel<<<NPT / 128, 256, smem>>>(pY1, pY2T, W2, b2);
        finalize_kernel<<<128, 128>>>(g2, be2, 2, NPT / 128);
    }
    // gather-max + BN2 + relu -> feature output
    final_kernel<<<(BB * SS) / 8, 256>>>(out_feat);
}